// round 5
// baseline (speedup 1.0000x reference)
#include <cuda_runtime.h>
#include <math.h>
#include <stdint.h>

// Problem constants (fixed by the reference: B=8, T=4096, D=1024)
constexpr int Bb   = 8;
constexpr int Tt   = 4096;
constexpr int Dd   = 1024;
constexpr int Mtot = Bb * Tt;          // 32768 rows
constexpr int NC   = 32;               // scan chunks
constexpr int CL   = Tt / NC;          // 128 steps per chunk

// Scratch (device globals — no allocations allowed in kernel_launch)
__device__ float sc_u[(size_t)Mtot * Dd];
__device__ float sc_g[(size_t)Mtot * Dd];
__device__ float sc_h[(size_t)Mtot * Dd];
__device__ float sc_P[Bb * NC * Dd];
__device__ float sc_S[Bb * NC * Dd];
__device__ float sc_C[Bb * NC * Dd];

// ===========================================================================
// tf32 mma.sync GEMM:  C[m,n] = sum_k A[m,k]*W[n,k] + bias[n]  (+sigmoid)
// R3 tile (proven): CTA 128x128, BK=16, 8 warps @ 64x32, occ 2.
// NEW vs R3: operands converted to tf32 ONCE at load (LDG->cvt.rna->STS,
// register-staged double buffer). Mainloop has ZERO cvt (was 48/warp/chunk,
// 4-way redundant) — fragments are plain LDS of tf32 bits.
// ===========================================================================
constexpr int BM = 128, BN = 128, BK = 16;
constexpr int NCHUNK = Dd / BK;        // 64
constexpr int LDP    = BK + 4;         // padded row stride (20, conflict-free)
constexpr int STGF   = BM * LDP;       // uint32 per matrix per stage

__device__ __forceinline__ uint32_t f2tf(float x) {
    uint32_t r;
    asm("cvt.rna.tf32.f32 %0, %1;" : "=r"(r) : "f"(x));
    return r;
}
__device__ __forceinline__ void mma8(float* d, const uint32_t* a, const uint32_t* b) {
    asm volatile(
        "mma.sync.aligned.m16n8k8.row.col.f32.tf32.tf32.f32 "
        "{%0,%1,%2,%3}, {%4,%5,%6,%7}, {%8,%9}, {%0,%1,%2,%3};"
        : "+f"(d[0]), "+f"(d[1]), "+f"(d[2]), "+f"(d[3])
        : "r"(a[0]), "r"(a[1]), "r"(a[2]), "r"(a[3]), "r"(b[0]), "r"(b[1]));
}
__device__ __forceinline__ uint4 cvt4(float4 v) {
    return make_uint4(f2tf(v.x), f2tf(v.y), f2tf(v.z), f2tf(v.w));
}

__global__ __launch_bounds__(256, 2)
void gemm_tc(const float* __restrict__ A, const float* __restrict__ W,
             const float* __restrict__ bias, float* __restrict__ C, int act)
{
    // tf32 bits, padded rows (stride 20): fragment-LDS bank map
    // {0,20,8,28,16,4,24,12}+lc covers all 32 banks — conflict-free.
    __shared__ __align__(16) uint32_t Asm[2][STGF];
    __shared__ __align__(16) uint32_t Bsm[2][STGF];

    const int tid  = threadIdx.x;
    const int wid  = tid >> 5;
    const int lane = tid & 31;
    const int lr   = lane >> 2;          // 0..7
    const int lc   = lane & 3;           // 0..3
    const int bnb  = blockIdx.x;         // N tile (0..7)
    const int bmb  = blockIdx.y;         // M tile (0..255)

    const int wm = (wid >> 2) * 64;      // warp M offset
    const int wn = (wid & 3) * 32;       // warp N offset

    // ---- loader mapping: thread -> row r (0..127), half h (8 floats) ----
    const int r = tid >> 1;
    const int h = tid & 1;
    const float4* A4 = reinterpret_cast<const float4*>(A)
                       + ((size_t)bmb * BM + r) * (Dd / 4) + h * 2;
    const float4* B4 = reinterpret_cast<const float4*>(W)
                       + ((size_t)bnb * BN + r) * (Dd / 4) + h * 2;
    const int stoff = r * LDP + h * 8;   // uint32 index in stage (16B aligned)

    float4 ra0, ra1, rb0, rb1;           // staged chunk (fp32 from LDG)

    #define LDG_CHUNK(c) do {                                                 \
        ra0 = A4[(c) * 4]; ra1 = A4[(c) * 4 + 1];                             \
        rb0 = B4[(c) * 4]; rb1 = B4[(c) * 4 + 1];                             \
    } while (0)

    #define STS_CHUNK(s) do {                                                 \
        *reinterpret_cast<uint4*>(&Asm[s][stoff])     = cvt4(ra0);            \
        *reinterpret_cast<uint4*>(&Asm[s][stoff + 4]) = cvt4(ra1);            \
        *reinterpret_cast<uint4*>(&Bsm[s][stoff])     = cvt4(rb0);            \
        *reinterpret_cast<uint4*>(&Bsm[s][stoff + 4]) = cvt4(rb1);            \
    } while (0)

    float acc[4][4][4] = {};

    // prologue: chunk0 -> stage0; chunk1 staged in regs
    LDG_CHUNK(0);
    STS_CHUNK(0);
    LDG_CHUNK(1);

    for (int c = 0; c < NCHUNK; c++) {
        const int s = c & 1;
        __syncthreads();                       // stage s ready, stage s^1 free

        if (c + 1 < NCHUNK) STS_CHUNK(s ^ 1);  // overlap with compute below
        if (c + 2 < NCHUNK) LDG_CHUNK(c + 2);

        const uint32_t* Ab = Asm[s];
        const uint32_t* Bb = Bsm[s];

        #pragma unroll
        for (int ks = 0; ks < 2; ks++) {
            const int k0 = ks * 8;
            uint32_t af[4][4], bf[4][2];
            #pragma unroll
            for (int mi = 0; mi < 4; mi++) {
                const int rr = wm + mi * 16 + lr;
                af[mi][0] = Ab[rr * LDP + k0 + lc];
                af[mi][1] = Ab[(rr + 8) * LDP + k0 + lc];
                af[mi][2] = Ab[rr * LDP + k0 + lc + 4];
                af[mi][3] = Ab[(rr + 8) * LDP + k0 + lc + 4];
            }
            #pragma unroll
            for (int ni = 0; ni < 4; ni++) {
                const int nr = wn + ni * 8 + lr;
                bf[ni][0] = Bb[nr * LDP + k0 + lc];
                bf[ni][1] = Bb[nr * LDP + k0 + lc + 4];
            }
            #pragma unroll
            for (int mi = 0; mi < 4; mi++)
                #pragma unroll
                for (int ni = 0; ni < 4; ni++)
                    mma8(acc[mi][ni], af[mi], bf[ni]);
        }
    }

    // ---- epilogue: bias (+sigmoid), float2 stores ----
    #pragma unroll
    for (int ni = 0; ni < 4; ni++) {
        const int gc = bnb * BN + wn + ni * 8 + lc * 2;
        const float b0 = bias[gc], b1 = bias[gc + 1];
        #pragma unroll
        for (int mi = 0; mi < 4; mi++) {
            const size_t gr = (size_t)bmb * BM + wm + mi * 16 + lr;
            float v0 = acc[mi][ni][0] + b0;
            float v1 = acc[mi][ni][1] + b1;
            float v2 = acc[mi][ni][2] + b0;
            float v3 = acc[mi][ni][3] + b1;
            if (act) {
                v0 = 1.0f / (1.0f + __expf(-v0));
                v1 = 1.0f / (1.0f + __expf(-v1));
                v2 = 1.0f / (1.0f + __expf(-v2));
                v3 = 1.0f / (1.0f + __expf(-v3));
            }
            *reinterpret_cast<float2*>(C + gr * Dd + gc)       = make_float2(v0, v1);
            *reinterpret_cast<float2*>(C + (gr + 8) * Dd + gc) = make_float2(v2, v3);
        }
    }
    #undef LDG_CHUNK
    #undef STS_CHUNK
}

// ---------------------------------------------------------------------------
// Chunked linear-recurrence scan: h_t = g_t*h_{t-1} + (1-g_t)*u_t
// ---------------------------------------------------------------------------
__global__ void scan_phase1()
{
    const int d = blockIdx.x * blockDim.x + threadIdx.x;
    const int c = blockIdx.y;
    const int b = blockIdx.z;
    const size_t base = ((size_t)b * Tt + (size_t)c * CL) * Dd + d;

    float P = 1.0f, S = 0.0f;
    #pragma unroll 4
    for (int t = 0; t < CL; ++t) {
        const float gg = sc_g[base + (size_t)t * Dd];
        const float uu = sc_u[base + (size_t)t * Dd];
        S = fmaf(gg, S, (1.0f - gg) * uu);
        P *= gg;
    }
    const int idx = (b * NC + c) * Dd + d;
    sc_P[idx] = P;
    sc_S[idx] = S;
}

__global__ void scan_phase2()
{
    const int idx = blockIdx.x * blockDim.x + threadIdx.x;
    const int b = idx >> 10;
    const int d = idx & 1023;

    float carry = 0.0f;
    #pragma unroll
    for (int c = 0; c < NC; ++c) {
        const int k = (b * NC + c) * Dd + d;
        sc_C[k] = carry;
        carry = fmaf(sc_P[k], carry, sc_S[k]);
    }
}

__global__ void scan_phase3()
{
    const int d = blockIdx.x * blockDim.x + threadIdx.x;
    const int c = blockIdx.y;
    const int b = blockIdx.z;
    const size_t base = ((size_t)b * Tt + (size_t)c * CL) * Dd + d;

    float h = sc_C[(b * NC + c) * Dd + d];
    #pragma unroll 4
    for (int t = 0; t < CL; ++t) {
        const float gg = sc_g[base + (size_t)t * Dd];
        const float uu = sc_u[base + (size_t)t * Dd];
        h = fmaf(gg, h, (1.0f - gg) * uu);
        sc_h[base + (size_t)t * Dd] = h;
    }
}

// ---------------------------------------------------------------------------
extern "C" void kernel_launch(void* const* d_in, const int* in_sizes, int n_in,
                              void* d_out, int out_size)
{
    (void)in_sizes; (void)n_in; (void)out_size;

    const float* x  = (const float*)d_in[0];
    const float* Wi = (const float*)d_in[1];
    const float* bi = (const float*)d_in[2];
    const float* Wg = (const float*)d_in[3];
    const float* bg = (const float*)d_in[4];
    const float* Wo = (const float*)d_in[5];
    const float* bo = (const float*)d_in[6];
    float* out = (float*)d_out;

    float *u, *g, *h;
    cudaGetSymbolAddress((void**)&u, sc_u);
    cudaGetSymbolAddress((void**)&g, sc_g);
    cudaGetSymbolAddress((void**)&h, sc_h);

    const dim3 ggrid(Dd / BN, Mtot / BM);   // (8, 256)
    const dim3 gblk(256);

    gemm_tc<<<ggrid, gblk>>>(x, Wi, bi, u, 0);
    gemm_tc<<<ggrid, gblk>>>(x, Wg, bg, g, 1);

    const dim3 s_grid(Dd / 256, NC, Bb);    // (4, 32, 8)
    scan_phase1<<<s_grid, 256>>>();
    scan_phase2<<<32, 256>>>();
    scan_phase3<<<s_grid, 256>>>();

    gemm_tc<<<ggrid, gblk>>>(h, Wo, bo, out, 0);
}

// round 6
// speedup vs baseline: 1.3525x; 1.3525x over previous
#include <cuda_runtime.h>
#include <math.h>
#include <stdint.h>

// Problem constants (fixed by the reference: B=8, T=4096, D=1024)
constexpr int Bb   = 8;
constexpr int Tt   = 4096;
constexpr int Dd   = 1024;
constexpr int Mtot = Bb * Tt;          // 32768 rows
constexpr int NC   = 32;               // scan chunks
constexpr int CL   = Tt / NC;          // 128 steps per chunk

// Scratch (device globals — no allocations allowed in kernel_launch)
__device__ float sc_u[(size_t)Mtot * Dd];
__device__ float sc_g[(size_t)Mtot * Dd];
__device__ float sc_h[(size_t)Mtot * Dd];
__device__ float lb_cv[Bb * NC * Dd];      // carry-out values per (b,chunk,d)
__device__ int   lb_flag[Bb * NC * 4];     // ready flags per (b,chunk,dblk)

// ===========================================================================
// tf32 mma.sync GEMM (exact R3 winner):
// C[m,n] = sum_k A[m,k]*W[n,k] + bias[n]  (+sigmoid)
// CTA 128x128, BK=16, 8 warps @ 64x32 (4x4 m16n8k8), cp.async double buffer,
// pad stride 20 (conflict-free). ~94% of the legacy HMMA tf32 pipe.
// ===========================================================================
constexpr int BM = 128, BN = 128, BK = 16;
constexpr int NCHUNK = Dd / BK;        // 64
constexpr int LDP    = BK + 4;         // padded row stride (floats)

__device__ __forceinline__ uint32_t smem_u32(const void* p) {
    uint32_t a;
    asm("{ .reg .u64 t; cvta.to.shared.u64 t, %1; cvt.u32.u64 %0, t; }"
        : "=r"(a) : "l"(p));
    return a;
}
__device__ __forceinline__ void cp16(uint32_t s, const void* g) {
    asm volatile("cp.async.cg.shared.global [%0], [%1], 16;" :: "r"(s), "l"(g));
}
__device__ __forceinline__ uint32_t f2tf(float x) {
    uint32_t r;
    asm("cvt.rna.tf32.f32 %0, %1;" : "=r"(r) : "f"(x));
    return r;
}
__device__ __forceinline__ void mma8(float* d, const uint32_t* a, const uint32_t* b) {
    asm volatile(
        "mma.sync.aligned.m16n8k8.row.col.f32.tf32.tf32.f32 "
        "{%0,%1,%2,%3}, {%4,%5,%6,%7}, {%8,%9}, {%0,%1,%2,%3};"
        : "+f"(d[0]), "+f"(d[1]), "+f"(d[2]), "+f"(d[3])
        : "r"(a[0]), "r"(a[1]), "r"(a[2]), "r"(a[3]), "r"(b[0]), "r"(b[1]));
}

__global__ __launch_bounds__(256, 2)
void gemm_tc(const float* __restrict__ A, const float* __restrict__ W,
             const float* __restrict__ bias, float* __restrict__ C, int act)
{
    __shared__ __align__(16) float As[2][BM][LDP];
    __shared__ __align__(16) float Bs[2][BN][LDP];

    const int tid  = threadIdx.x;
    const int wid  = tid >> 5;
    const int lane = tid & 31;
    const int lr   = lane >> 2;          // 0..7
    const int lc   = lane & 3;           // 0..3
    const int bnb  = blockIdx.x;         // N tile (0..7)
    const int bmb  = blockIdx.y;         // M tile (0..255)

    const int wm = (wid >> 2) * 64;      // warp M offset in tile
    const int wn = (wid & 3) * 32;       // warp N offset in tile

    const int r0 = tid >> 2,  q0 = tid & 3;
    const int r1 = r0 + 64;
    const float4* A4 = reinterpret_cast<const float4*>(A) + ((size_t)bmb * BM) * (Dd / 4);
    const float4* B4 = reinterpret_cast<const float4*>(W) + ((size_t)bnb * BN) * (Dd / 4);

    uint32_t sA0[2], sA1[2], sB0[2], sB1[2];
    {
        const uint32_t ab = smem_u32(&As[0][0][0]);
        const uint32_t bb = smem_u32(&Bs[0][0][0]);
        #pragma unroll
        for (int s = 0; s < 2; s++) {
            sA0[s] = ab + ((s * BM + r0) * LDP + q0 * 4) * 4;
            sA1[s] = ab + ((s * BM + r1) * LDP + q0 * 4) * 4;
            sB0[s] = bb + ((s * BN + r0) * LDP + q0 * 4) * 4;
            sB1[s] = bb + ((s * BN + r1) * LDP + q0 * 4) * 4;
        }
    }

    #define LOAD_STAGE(c, s) do {                                            \
        const float4* ga0 = A4 + (size_t)r0 * (Dd / 4) + (c) * 4 + q0;        \
        const float4* ga1 = A4 + (size_t)r1 * (Dd / 4) + (c) * 4 + q0;        \
        const float4* gb0 = B4 + (size_t)r0 * (Dd / 4) + (c) * 4 + q0;        \
        const float4* gb1 = B4 + (size_t)r1 * (Dd / 4) + (c) * 4 + q0;        \
        cp16(sA0[s], ga0); cp16(sA1[s], ga1);                                 \
        cp16(sB0[s], gb0); cp16(sB1[s], gb1);                                 \
        asm volatile("cp.async.commit_group;");                               \
    } while (0)

    float acc[4][4][4] = {};

    LOAD_STAGE(0, 0);
    LOAD_STAGE(1, 1);

    for (int c = 0; c < NCHUNK; c++) {
        const int s = c & 1;
        if (c + 1 < NCHUNK) asm volatile("cp.async.wait_group 1;" ::: "memory");
        else                asm volatile("cp.async.wait_group 0;" ::: "memory");
        __syncthreads();

        #pragma unroll
        for (int ks = 0; ks < 2; ks++) {
            const int k0 = ks * 8;
            uint32_t af[4][4], bf[4][2];
            #pragma unroll
            for (int mi = 0; mi < 4; mi++) {
                const int rr = wm + mi * 16 + lr;
                af[mi][0] = f2tf(As[s][rr    ][k0 + lc]);
                af[mi][1] = f2tf(As[s][rr + 8][k0 + lc]);
                af[mi][2] = f2tf(As[s][rr    ][k0 + lc + 4]);
                af[mi][3] = f2tf(As[s][rr + 8][k0 + lc + 4]);
            }
            #pragma unroll
            for (int ni = 0; ni < 4; ni++) {
                const int nr = wn + ni * 8 + lr;
                bf[ni][0] = f2tf(Bs[s][nr][k0 + lc]);
                bf[ni][1] = f2tf(Bs[s][nr][k0 + lc + 4]);
            }
            #pragma unroll
            for (int mi = 0; mi < 4; mi++)
                #pragma unroll
                for (int ni = 0; ni < 4; ni++)
                    mma8(acc[mi][ni], af[mi], bf[ni]);
        }

        __syncthreads();
        if (c + 2 < NCHUNK) LOAD_STAGE(c + 2, s);
    }

    #pragma unroll
    for (int ni = 0; ni < 4; ni++) {
        const int gc = bnb * BN + wn + ni * 8 + lc * 2;
        const float b0 = bias[gc], b1 = bias[gc + 1];
        #pragma unroll
        for (int mi = 0; mi < 4; mi++) {
            const size_t gr = (size_t)bmb * BM + wm + mi * 16 + lr;
            float v0 = acc[mi][ni][0] + b0;
            float v1 = acc[mi][ni][1] + b1;
            float v2 = acc[mi][ni][2] + b0;
            float v3 = acc[mi][ni][3] + b1;
            if (act) {
                v0 = 1.0f / (1.0f + __expf(-v0));
                v1 = 1.0f / (1.0f + __expf(-v1));
                v2 = 1.0f / (1.0f + __expf(-v2));
                v3 = 1.0f / (1.0f + __expf(-v3));
            }
            *reinterpret_cast<float2*>(C + gr * Dd + gc)       = make_float2(v0, v1);
            *reinterpret_cast<float2*>(C + (gr + 8) * Dd + gc) = make_float2(v2, v3);
        }
    }
    #undef LOAD_STAGE
}

// ---------------------------------------------------------------------------
// Fused single-pass scan with decoupled lookback.
// h_t = g_t*h_{t-1} + (1-g_t)*u_t.
// Block (xb, c, b): 256 d-lanes of chunk c. Local pass -> wait predecessor
// carry (flag+value) -> publish carry-out -> replay writing h.
// All 1024 blocks are co-resident (256 thr, tiny smem/regs), so the spin
// cannot deadlock regardless of scheduling order.
// ---------------------------------------------------------------------------
__global__ __launch_bounds__(256, 8)
void scan_fused()
{
    const int xb = blockIdx.x;                 // 0..3 (d block)
    const int c  = blockIdx.y;                 // 0..31 (chunk)
    const int b  = blockIdx.z;                 // 0..7
    const int d  = xb * 256 + threadIdx.x;
    const size_t base = ((size_t)b * Tt + (size_t)c * CL) * Dd + d;

    // local pass: chunk transfer function (P = prod g, S = local h from 0)
    float P = 1.0f, S = 0.0f;
    #pragma unroll 4
    for (int t = 0; t < CL; ++t) {
        const float gg = sc_g[base + (size_t)t * Dd];
        const float uu = sc_u[base + (size_t)t * Dd];
        S = fmaf(gg, S, (1.0f - gg) * uu);
        P *= gg;
    }

    // wait for predecessor chunk's carry-out
    float carry = 0.0f;
    if (c > 0) {
        const int pf = (b * NC + (c - 1)) * 4 + xb;
        if (threadIdx.x == 0) {
            while (atomicAdd(&lb_flag[pf], 0) == 0) { }
        }
        __syncthreads();
        __threadfence();
        carry = lb_cv[(b * NC + (c - 1)) * Dd + d];
    }

    // publish my carry-out
    lb_cv[(b * NC + c) * Dd + d] = fmaf(P, carry, S);
    __threadfence();
    __syncthreads();
    if (threadIdx.x == 0)
        atomicExch(&lb_flag[(b * NC + c) * 4 + xb], 1);

    // replay from carry-in, writing h
    float h = carry;
    #pragma unroll 4
    for (int t = 0; t < CL; ++t) {
        const float gg = sc_g[base + (size_t)t * Dd];
        const float uu = sc_u[base + (size_t)t * Dd];
        h = fmaf(gg, h, (1.0f - gg) * uu);
        sc_h[base + (size_t)t * Dd] = h;
    }
}

// ---------------------------------------------------------------------------
extern "C" void kernel_launch(void* const* d_in, const int* in_sizes, int n_in,
                              void* d_out, int out_size)
{
    (void)in_sizes; (void)n_in; (void)out_size;

    const float* x  = (const float*)d_in[0];
    const float* Wi = (const float*)d_in[1];
    const float* bi = (const float*)d_in[2];
    const float* Wg = (const float*)d_in[3];
    const float* bg = (const float*)d_in[4];
    const float* Wo = (const float*)d_in[5];
    const float* bo = (const float*)d_in[6];
    float* out = (float*)d_out;

    float *u, *g, *h;
    void* flags;
    cudaGetSymbolAddress((void**)&u, sc_u);
    cudaGetSymbolAddress((void**)&g, sc_g);
    cudaGetSymbolAddress((void**)&h, sc_h);
    cudaGetSymbolAddress(&flags, lb_flag);

    // reset lookback flags (graph-capturable async memset, 4KB)
    cudaMemsetAsync(flags, 0, Bb * NC * 4 * sizeof(int));

    const dim3 ggrid(Dd / BN, Mtot / BM);   // (8, 256)
    const dim3 gblk(256);

    gemm_tc<<<ggrid, gblk>>>(x, Wi, bi, u, 0);
    gemm_tc<<<ggrid, gblk>>>(x, Wg, bg, g, 1);

    scan_fused<<<dim3(4, NC, Bb), 256>>>();

    gemm_tc<<<ggrid, gblk>>>(h, Wo, bo, out, 0);
}

// round 7
// speedup vs baseline: 1.3917x; 1.0290x over previous
#include <cuda_runtime.h>
#include <math.h>
#include <stdint.h>

// Problem constants (fixed by the reference: B=8, T=4096, D=1024)
constexpr int Bb   = 8;
constexpr int Tt   = 4096;
constexpr int Dd   = 1024;
constexpr int Mtot = Bb * Tt;          // 32768 rows
constexpr int NC   = 32;               // scan chunks
constexpr int CL   = Tt / NC;          // 128 steps per chunk

// Scratch (device globals — no allocations allowed in kernel_launch)
__device__ float sc_u[(size_t)Mtot * Dd];
__device__ float sc_g[(size_t)Mtot * Dd];
__device__ float sc_h[(size_t)Mtot * Dd];    // written tf32-rounded by scan p3
__device__ float sc_xt[(size_t)Mtot * Dd];   // x rounded to tf32 bits
__device__ float sc_wt[3][(size_t)Dd * Dd];  // Wi/Wg/Wo rounded to tf32 bits
__device__ float sc_P[Bb * NC * Dd];
__device__ float sc_S[Bb * NC * Dd];
__device__ float sc_C[Bb * NC * Dd];

__device__ __forceinline__ uint32_t f2tf(float x) {
    uint32_t r;
    asm("cvt.rna.tf32.f32 %0, %1;" : "=r"(r) : "f"(x));
    return r;
}
__device__ __forceinline__ float f2tf_f(float x) { return __uint_as_float(f2tf(x)); }

// ---------------------------------------------------------------------------
// Pre-round fp32 -> tf32 bits (grid-stride, float4)
// ---------------------------------------------------------------------------
__global__ void round_tf32_k(const float4* __restrict__ in, float4* __restrict__ out,
                             int n4)
{
    const int stride = gridDim.x * blockDim.x;
    for (int i = blockIdx.x * blockDim.x + threadIdx.x; i < n4; i += stride) {
        float4 v = in[i];
        out[i] = make_float4(f2tf_f(v.x), f2tf_f(v.y), f2tf_f(v.z), f2tf_f(v.w));
    }
}

// ===========================================================================
// tf32 mma.sync GEMM on PRE-ROUNDED operands:
// C[m,n] = sum_k A[m,k]*W[n,k] + bias[n]  (+sigmoid)
// R3 pipeline (CTA 128x128, BK=16, 8 warps @ 64x32, cp.async 2-stage,
// stride-20 pad) with fragments via ldmatrix.x4 (b16 view of tf32) and
// ZERO cvt in the mainloop.
// ===========================================================================
constexpr int BM = 128, BN = 128, BK = 16;
constexpr int NCHUNK = Dd / BK;        // 64
constexpr int LDP    = BK + 4;         // padded row stride (floats)
constexpr int STGB   = BM * LDP * 4;   // stage bytes per matrix

__device__ __forceinline__ uint32_t smem_u32(const void* p) {
    uint32_t a;
    asm("{ .reg .u64 t; cvta.to.shared.u64 t, %1; cvt.u32.u64 %0, t; }"
        : "=r"(a) : "l"(p));
    return a;
}
__device__ __forceinline__ void cp16(uint32_t s, const void* g) {
    asm volatile("cp.async.cg.shared.global [%0], [%1], 16;" :: "r"(s), "l"(g));
}
__device__ __forceinline__ void ldsm4(uint32_t& r0, uint32_t& r1, uint32_t& r2,
                                      uint32_t& r3, uint32_t addr) {
    asm volatile("ldmatrix.sync.aligned.m8n8.x4.shared.b16 {%0,%1,%2,%3}, [%4];"
                 : "=r"(r0), "=r"(r1), "=r"(r2), "=r"(r3) : "r"(addr));
}
__device__ __forceinline__ void mma8(float* d, const uint32_t* a, const uint32_t* b) {
    asm volatile(
        "mma.sync.aligned.m16n8k8.row.col.f32.tf32.tf32.f32 "
        "{%0,%1,%2,%3}, {%4,%5,%6,%7}, {%8,%9}, {%0,%1,%2,%3};"
        : "+f"(d[0]), "+f"(d[1]), "+f"(d[2]), "+f"(d[3])
        : "r"(a[0]), "r"(a[1]), "r"(a[2]), "r"(a[3]), "r"(b[0]), "r"(b[1]));
}

__global__ __launch_bounds__(256, 2)
void gemm_tc(const float* __restrict__ A, const float* __restrict__ W,
             const float* __restrict__ bias, float* __restrict__ C, int act)
{
    __shared__ __align__(16) float As[2][BM][LDP];
    __shared__ __align__(16) float Bs[2][BN][LDP];

    const int tid  = threadIdx.x;
    const int wid  = tid >> 5;
    const int lane = tid & 31;
    const int lr   = lane >> 2;          // 0..7
    const int lc   = lane & 3;           // 0..3
    const int bnb  = blockIdx.x;         // N tile (0..7)
    const int bmb  = blockIdx.y;         // M tile (0..255)

    const int wm = (wid >> 2) * 64;      // warp M offset in tile
    const int wn = (wid & 3) * 32;       // warp N offset in tile

    // ---- cp.async loader mapping (as R3) ----
    const int r0 = tid >> 2,  q0 = tid & 3;
    const int r1 = r0 + 64;
    const float4* A4 = reinterpret_cast<const float4*>(A) + ((size_t)bmb * BM) * (Dd / 4);
    const float4* B4 = reinterpret_cast<const float4*>(W) + ((size_t)bnb * BN) * (Dd / 4);

    const uint32_t abase = smem_u32(&As[0][0][0]);
    const uint32_t bbase = smem_u32(&Bs[0][0][0]);

    uint32_t sA0[2], sA1[2], sB0[2], sB1[2];
    #pragma unroll
    for (int s = 0; s < 2; s++) {
        sA0[s] = abase + ((s * BM + r0) * LDP + q0 * 4) * 4;
        sA1[s] = abase + ((s * BM + r1) * LDP + q0 * 4) * 4;
        sB0[s] = bbase + ((s * BN + r0) * LDP + q0 * 4) * 4;
        sB1[s] = bbase + ((s * BN + r1) * LDP + q0 * 4) * 4;
    }

    // ---- ldmatrix per-lane base addresses ----
    // A x4 (per mi,ks): matrices {rows 0-7 | rows 8-15} x {cols k0 | k0+4}
    //   lane -> row (lane&15), col-group (lane>>4)
    const uint32_t aFrag = abase + (((wm + (lane & 15)) * LDP + (lane >> 4) * 4) * 4);
    // B x4 (per ni-pair,ks): {ni rows, col k0 | ni rows, col k0+4 |
    //                         ni+1 rows, col k0 | ni+1 rows, col k0+4}
    //   lane -> row (lane&7) + (lane>>4)*8, col-group ((lane>>3)&1)
    const uint32_t bFrag = bbase + (((wn + (lane & 7) + (lane >> 4) * 8) * LDP
                                     + ((lane >> 3) & 1) * 4) * 4);

    #define LOAD_STAGE(c, s) do {                                            \
        const float4* ga0 = A4 + (size_t)r0 * (Dd / 4) + (c) * 4 + q0;        \
        const float4* ga1 = A4 + (size_t)r1 * (Dd / 4) + (c) * 4 + q0;        \
        const float4* gb0 = B4 + (size_t)r0 * (Dd / 4) + (c) * 4 + q0;        \
        const float4* gb1 = B4 + (size_t)r1 * (Dd / 4) + (c) * 4 + q0;        \
        cp16(sA0[s], ga0); cp16(sA1[s], ga1);                                 \
        cp16(sB0[s], gb0); cp16(sB1[s], gb1);                                 \
        asm volatile("cp.async.commit_group;");                               \
    } while (0)

    float acc[4][4][4] = {};

    LOAD_STAGE(0, 0);
    LOAD_STAGE(1, 1);

    for (int c = 0; c < NCHUNK; c++) {
        const int s = c & 1;
        if (c + 1 < NCHUNK) asm volatile("cp.async.wait_group 1;" ::: "memory");
        else                asm volatile("cp.async.wait_group 0;" ::: "memory");
        __syncthreads();

        const uint32_t aS = aFrag + (uint32_t)s * STGB;
        const uint32_t bS = bFrag + (uint32_t)s * STGB;

        #pragma unroll
        for (int ks = 0; ks < 2; ks++) {
            const uint32_t ko = (uint32_t)ks * 32;   // k0*4 bytes
            uint32_t af[4][4], bf[4][2];
            #pragma unroll
            for (int mi = 0; mi < 4; mi++)
                ldsm4(af[mi][0], af[mi][1], af[mi][2], af[mi][3],
                      aS + (uint32_t)mi * (16 * LDP * 4) + ko);
            #pragma unroll
            for (int p = 0; p < 2; p++)
                ldsm4(bf[2 * p][0], bf[2 * p][1], bf[2 * p + 1][0], bf[2 * p + 1][1],
                      bS + (uint32_t)p * (16 * LDP * 4) + ko);
            #pragma unroll
            for (int mi = 0; mi < 4; mi++)
                #pragma unroll
                for (int ni = 0; ni < 4; ni++)
                    mma8(acc[mi][ni], af[mi], bf[ni]);
        }

        __syncthreads();
        if (c + 2 < NCHUNK) LOAD_STAGE(c + 2, s);
    }

    // ---- epilogue: bias (+sigmoid), float2 stores ----
    #pragma unroll
    for (int ni = 0; ni < 4; ni++) {
        const int gc = bnb * BN + wn + ni * 8 + lc * 2;
        const float b0 = bias[gc], b1 = bias[gc + 1];
        #pragma unroll
        for (int mi = 0; mi < 4; mi++) {
            const size_t gr = (size_t)bmb * BM + wm + mi * 16 + lr;
            float v0 = acc[mi][ni][0] + b0;
            float v1 = acc[mi][ni][1] + b1;
            float v2 = acc[mi][ni][2] + b0;
            float v3 = acc[mi][ni][3] + b1;
            if (act) {
                v0 = 1.0f / (1.0f + __expf(-v0));
                v1 = 1.0f / (1.0f + __expf(-v1));
                v2 = 1.0f / (1.0f + __expf(-v2));
                v3 = 1.0f / (1.0f + __expf(-v3));
            }
            *reinterpret_cast<float2*>(C + gr * Dd + gc)       = make_float2(v0, v1);
            *reinterpret_cast<float2*>(C + (gr + 8) * Dd + gc) = make_float2(v2, v3);
        }
    }
    #undef LOAD_STAGE
}

// ---------------------------------------------------------------------------
// Chunked linear-recurrence scan (proven 3-phase): h_t = g_t*h_{t-1}+(1-g_t)*u_t
// phase3 writes h PRE-ROUNDED to tf32 (h feeds only GEMM3; identical numerics
// to rounding at fragment load).
// ---------------------------------------------------------------------------
__global__ void scan_phase1()
{
    const int d = blockIdx.x * blockDim.x + threadIdx.x;
    const int c = blockIdx.y;
    const int b = blockIdx.z;
    const size_t base = ((size_t)b * Tt + (size_t)c * CL) * Dd + d;

    float P = 1.0f, S = 0.0f;
    #pragma unroll 4
    for (int t = 0; t < CL; ++t) {
        const float gg = sc_g[base + (size_t)t * Dd];
        const float uu = sc_u[base + (size_t)t * Dd];
        S = fmaf(gg, S, (1.0f - gg) * uu);
        P *= gg;
    }
    const int idx = (b * NC + c) * Dd + d;
    sc_P[idx] = P;
    sc_S[idx] = S;
}

__global__ void scan_phase2()
{
    const int idx = blockIdx.x * blockDim.x + threadIdx.x;
    const int b = idx >> 10;
    const int d = idx & 1023;

    float carry = 0.0f;
    #pragma unroll
    for (int c = 0; c < NC; ++c) {
        const int k = (b * NC + c) * Dd + d;
        sc_C[k] = carry;
        carry = fmaf(sc_P[k], carry, sc_S[k]);
    }
}

__global__ void scan_phase3()
{
    const int d = blockIdx.x * blockDim.x + threadIdx.x;
    const int c = blockIdx.y;
    const int b = blockIdx.z;
    const size_t base = ((size_t)b * Tt + (size_t)c * CL) * Dd + d;

    float h = sc_C[(b * NC + c) * Dd + d];
    #pragma unroll 4
    for (int t = 0; t < CL; ++t) {
        const float gg = sc_g[base + (size_t)t * Dd];
        const float uu = sc_u[base + (size_t)t * Dd];
        h = fmaf(gg, h, (1.0f - gg) * uu);
        sc_h[base + (size_t)t * Dd] = f2tf_f(h);
    }
}

// ---------------------------------------------------------------------------
extern "C" void kernel_launch(void* const* d_in, const int* in_sizes, int n_in,
                              void* d_out, int out_size)
{
    (void)in_sizes; (void)n_in; (void)out_size;

    const float* x  = (const float*)d_in[0];
    const float* Wi = (const float*)d_in[1];
    const float* bi = (const float*)d_in[2];
    const float* Wg = (const float*)d_in[3];
    const float* bg = (const float*)d_in[4];
    const float* Wo = (const float*)d_in[5];
    const float* bo = (const float*)d_in[6];
    float* out = (float*)d_out;

    float *u, *g, *h, *xt, *wt;
    cudaGetSymbolAddress((void**)&u,  sc_u);
    cudaGetSymbolAddress((void**)&g,  sc_g);
    cudaGetSymbolAddress((void**)&h,  sc_h);
    cudaGetSymbolAddress((void**)&xt, sc_xt);
    cudaGetSymbolAddress((void**)&wt, sc_wt);
    float* wti = wt;
    float* wtg = wt + (size_t)Dd * Dd;
    float* wto = wt + 2 * (size_t)Dd * Dd;

    // pre-round operands to tf32 bits
    round_tf32_k<<<4096, 256>>>((const float4*)x,  (float4*)xt,  Mtot * Dd / 4);
    round_tf32_k<<<512, 256>>>((const float4*)Wi, (float4*)wti, Dd * Dd / 4);
    round_tf32_k<<<512, 256>>>((const float4*)Wg, (float4*)wtg, Dd * Dd / 4);
    round_tf32_k<<<512, 256>>>((const float4*)Wo, (float4*)wto, Dd * Dd / 4);

    const dim3 ggrid(Dd / BN, Mtot / BM);   // (8, 256)
    const dim3 gblk(256);

    gemm_tc<<<ggrid, gblk>>>(xt, wti, bi, u, 0);
    gemm_tc<<<ggrid, gblk>>>(xt, wtg, bg, g, 1);

    const dim3 s_grid(Dd / 256, NC, Bb);    // (4, 32, 8)
    scan_phase1<<<s_grid, 256>>>();
    scan_phase2<<<32, 256>>>();
    scan_phase3<<<s_grid, 256>>>();

    gemm_tc<<<ggrid, gblk>>>(h, wto, bo, out, 0);
}

// round 8
// speedup vs baseline: 1.4788x; 1.0626x over previous
#include <cuda_runtime.h>
#include <math.h>
#include <stdint.h>

// Problem constants (fixed by the reference: B=8, T=4096, D=1024)
constexpr int Bb   = 8;
constexpr int Tt   = 4096;
constexpr int Dd   = 1024;
constexpr int Mtot = Bb * Tt;          // 32768 rows
constexpr int NC   = 32;               // scan chunks
constexpr int CL   = Tt / NC;          // 128 steps per chunk

// Scratch (device globals — no allocations allowed in kernel_launch)
__device__ float sc_u[(size_t)Mtot * Dd];
__device__ float sc_g[(size_t)Mtot * Dd];
__device__ float sc_h[(size_t)Mtot * Dd];    // written tf32-rounded by scan p3
__device__ float sc_xt[(size_t)Mtot * Dd];   // x rounded to tf32 bits
__device__ float sc_wt[3][(size_t)Dd * Dd];  // Wi/Wg/Wo rounded to tf32 bits
__device__ float sc_P[Bb * NC * Dd];
__device__ float sc_S[Bb * NC * Dd];
__device__ float sc_C[Bb * NC * Dd];

__device__ __forceinline__ uint32_t f2tf(float x) {
    uint32_t r;
    asm("cvt.rna.tf32.f32 %0, %1;" : "=r"(r) : "f"(x));
    return r;
}
__device__ __forceinline__ float f2tf_f(float x) { return __uint_as_float(f2tf(x)); }

// ---------------------------------------------------------------------------
// Pre-round fp32 -> tf32 bits (grid-stride, float4)
// ---------------------------------------------------------------------------
__global__ void round_tf32_k(const float4* __restrict__ in, float4* __restrict__ out,
                             int n4)
{
    const int stride = gridDim.x * blockDim.x;
    for (int i = blockIdx.x * blockDim.x + threadIdx.x; i < n4; i += stride) {
        float4 v = in[i];
        out[i] = make_float4(f2tf_f(v.x), f2tf_f(v.y), f2tf_f(v.z), f2tf_f(v.w));
    }
}

// ===========================================================================
// tf32 mma.sync GEMM on PRE-ROUNDED operands:
// C[m,n] = sum_k A[m,k]*W[n,k] + bias[n]  (+sigmoid)
// CTA 128x128, BK=16, 8 warps @ 64x32. NEW vs R7: 3-stage cp.async pipeline
// (60KB dynamic SMEM) with ONE __syncthreads per chunk and prefetch distance
// 2 — barrier count halved, load-latency slack doubled.
// ===========================================================================
constexpr int BM = 128, BN = 128, BK = 16;
constexpr int NCHUNK = Dd / BK;        // 64
constexpr int LDP    = BK + 4;         // padded row stride (floats)
constexpr int STGB   = BM * LDP * 4;   // stage bytes per matrix (10240)
constexpr int NSTG   = 3;
constexpr int SMEM_BYTES = 2 * NSTG * STGB;   // 61440

__device__ __forceinline__ uint32_t smem_u32(const void* p) {
    uint32_t a;
    asm("{ .reg .u64 t; cvta.to.shared.u64 t, %1; cvt.u32.u64 %0, t; }"
        : "=r"(a) : "l"(p));
    return a;
}
__device__ __forceinline__ void cp16(uint32_t s, const void* g) {
    asm volatile("cp.async.cg.shared.global [%0], [%1], 16;" :: "r"(s), "l"(g));
}
__device__ __forceinline__ void ldsm4(uint32_t& r0, uint32_t& r1, uint32_t& r2,
                                      uint32_t& r3, uint32_t addr) {
    asm volatile("ldmatrix.sync.aligned.m8n8.x4.shared.b16 {%0,%1,%2,%3}, [%4];"
                 : "=r"(r0), "=r"(r1), "=r"(r2), "=r"(r3) : "r"(addr));
}
__device__ __forceinline__ void mma8(float* d, const uint32_t* a, const uint32_t* b) {
    asm volatile(
        "mma.sync.aligned.m16n8k8.row.col.f32.tf32.tf32.f32 "
        "{%0,%1,%2,%3}, {%4,%5,%6,%7}, {%8,%9}, {%0,%1,%2,%3};"
        : "+f"(d[0]), "+f"(d[1]), "+f"(d[2]), "+f"(d[3])
        : "r"(a[0]), "r"(a[1]), "r"(a[2]), "r"(a[3]), "r"(b[0]), "r"(b[1]));
}

__global__ __launch_bounds__(256, 2)
void gemm_tc(const float* __restrict__ A, const float* __restrict__ W,
             const float* __restrict__ bias, float* __restrict__ C, int act)
{
    extern __shared__ float dynsm[];
    float* Asm = dynsm;                         // [NSTG][BM][LDP]
    float* Bsm = dynsm + NSTG * BM * LDP;       // [NSTG][BN][LDP]

    const int tid  = threadIdx.x;
    const int wid  = tid >> 5;
    const int lane = tid & 31;
    const int lr   = lane >> 2;          // 0..7
    const int lc   = lane & 3;           // 0..3
    const int bnb  = blockIdx.x;         // N tile (0..7)
    const int bmb  = blockIdx.y;         // M tile (0..255)

    const int wm = (wid >> 2) * 64;      // warp M offset in tile
    const int wn = (wid & 3) * 32;       // warp N offset in tile

    // ---- cp.async loader mapping ----
    const int r0 = tid >> 2,  q0 = tid & 3;
    const int r1 = r0 + 64;
    const float4* A4 = reinterpret_cast<const float4*>(A) + ((size_t)bmb * BM) * (Dd / 4);
    const float4* B4 = reinterpret_cast<const float4*>(W) + ((size_t)bnb * BN) * (Dd / 4);

    const uint32_t abase = smem_u32(Asm);
    const uint32_t bbase = smem_u32(Bsm);

    uint32_t sA0[NSTG], sA1[NSTG], sB0[NSTG], sB1[NSTG];
    #pragma unroll
    for (int s = 0; s < NSTG; s++) {
        sA0[s] = abase + ((s * BM + r0) * LDP + q0 * 4) * 4;
        sA1[s] = abase + ((s * BM + r1) * LDP + q0 * 4) * 4;
        sB0[s] = bbase + ((s * BN + r0) * LDP + q0 * 4) * 4;
        sB1[s] = bbase + ((s * BN + r1) * LDP + q0 * 4) * 4;
    }

    // ---- ldmatrix per-lane base addresses (stage 0) ----
    const uint32_t aFrag = abase + (((wm + (lane & 15)) * LDP + (lane >> 4) * 4) * 4);
    const uint32_t bFrag = bbase + (((wn + (lane & 7) + (lane >> 4) * 8) * LDP
                                     + ((lane >> 3) & 1) * 4) * 4);

    #define LOAD_STAGE(c, s) do {                                            \
        const float4* ga0 = A4 + (size_t)r0 * (Dd / 4) + (c) * 4 + q0;        \
        const float4* ga1 = A4 + (size_t)r1 * (Dd / 4) + (c) * 4 + q0;        \
        const float4* gb0 = B4 + (size_t)r0 * (Dd / 4) + (c) * 4 + q0;        \
        const float4* gb1 = B4 + (size_t)r1 * (Dd / 4) + (c) * 4 + q0;        \
        cp16(sA0[s], ga0); cp16(sA1[s], ga1);                                 \
        cp16(sB0[s], gb0); cp16(sB1[s], gb1);                                 \
        asm volatile("cp.async.commit_group;");                               \
    } while (0)

    float acc[4][4][4] = {};

    // prologue: chunks 0,1 in flight
    LOAD_STAGE(0, 0);
    LOAD_STAGE(1, 1);

    int s = 0;                 // stage of chunk c
    for (int c = 0; c < NCHUNK; c++) {
        // chunk c landed (chunk c+1 may still be in flight)
        if (c + 1 < NCHUNK) asm volatile("cp.async.wait_group 1;" ::: "memory");
        else                asm volatile("cp.async.wait_group 0;" ::: "memory");
        // one barrier per chunk: (i) stage c visible to all warps,
        // (ii) stage (c+2)%3 = (c-1)%3 fully consumed -> safe to overwrite
        __syncthreads();

        if (c + 2 < NCHUNK) {
            const int sn = (s + 2 >= NSTG) ? s + 2 - NSTG : s + 2;
            LOAD_STAGE(c + 2, sn);
        }

        const uint32_t aS = aFrag + (uint32_t)s * STGB;
        const uint32_t bS = bFrag + (uint32_t)s * STGB;

        #pragma unroll
        for (int ks = 0; ks < 2; ks++) {
            const uint32_t ko = (uint32_t)ks * 32;   // k0*4 bytes
            uint32_t af[4][4], bf[4][2];
            #pragma unroll
            for (int mi = 0; mi < 4; mi++)
                ldsm4(af[mi][0], af[mi][1], af[mi][2], af[mi][3],
                      aS + (uint32_t)mi * (16 * LDP * 4) + ko);
            #pragma unroll
            for (int p = 0; p < 2; p++)
                ldsm4(bf[2 * p][0], bf[2 * p][1], bf[2 * p + 1][0], bf[2 * p + 1][1],
                      bS + (uint32_t)p * (16 * LDP * 4) + ko);
            #pragma unroll
            for (int mi = 0; mi < 4; mi++)
                #pragma unroll
                for (int ni = 0; ni < 4; ni++)
                    mma8(acc[mi][ni], af[mi], bf[ni]);
        }

        s = (s + 1 >= NSTG) ? 0 : s + 1;
    }

    // ---- epilogue: bias (+sigmoid), float2 stores ----
    #pragma unroll
    for (int ni = 0; ni < 4; ni++) {
        const int gc = bnb * BN + wn + ni * 8 + lc * 2;
        const float b0 = bias[gc], b1 = bias[gc + 1];
        #pragma unroll
        for (int mi = 0; mi < 4; mi++) {
            const size_t gr = (size_t)bmb * BM + wm + mi * 16 + lr;
            float v0 = acc[mi][ni][0] + b0;
            float v1 = acc[mi][ni][1] + b1;
            float v2 = acc[mi][ni][2] + b0;
            float v3 = acc[mi][ni][3] + b1;
            if (act) {
                v0 = 1.0f / (1.0f + __expf(-v0));
                v1 = 1.0f / (1.0f + __expf(-v1));
                v2 = 1.0f / (1.0f + __expf(-v2));
                v3 = 1.0f / (1.0f + __expf(-v3));
            }
            *reinterpret_cast<float2*>(C + gr * Dd + gc)       = make_float2(v0, v1);
            *reinterpret_cast<float2*>(C + (gr + 8) * Dd + gc) = make_float2(v2, v3);
        }
    }
    #undef LOAD_STAGE
}

// ---------------------------------------------------------------------------
// Chunked linear-recurrence scan (proven 3-phase): h_t = g_t*h_{t-1}+(1-g_t)*u_t
// phase3 writes h PRE-ROUNDED to tf32 (h feeds only GEMM3).
// ---------------------------------------------------------------------------
__global__ void scan_phase1()
{
    const int d = blockIdx.x * blockDim.x + threadIdx.x;
    const int c = blockIdx.y;
    const int b = blockIdx.z;
    const size_t base = ((size_t)b * Tt + (size_t)c * CL) * Dd + d;

    float P = 1.0f, S = 0.0f;
    #pragma unroll 4
    for (int t = 0; t < CL; ++t) {
        const float gg = sc_g[base + (size_t)t * Dd];
        const float uu = sc_u[base + (size_t)t * Dd];
        S = fmaf(gg, S, (1.0f - gg) * uu);
        P *= gg;
    }
    const int idx = (b * NC + c) * Dd + d;
    sc_P[idx] = P;
    sc_S[idx] = S;
}

__global__ void scan_phase2()
{
    const int idx = blockIdx.x * blockDim.x + threadIdx.x;
    const int b = idx >> 10;
    const int d = idx & 1023;

    float carry = 0.0f;
    #pragma unroll
    for (int c = 0; c < NC; ++c) {
        const int k = (b * NC + c) * Dd + d;
        sc_C[k] = carry;
        carry = fmaf(sc_P[k], carry, sc_S[k]);
    }
}

__global__ void scan_phase3()
{
    const int d = blockIdx.x * blockDim.x + threadIdx.x;
    const int c = blockIdx.y;
    const int b = blockIdx.z;
    const size_t base = ((size_t)b * Tt + (size_t)c * CL) * Dd + d;

    float h = sc_C[(b * NC + c) * Dd + d];
    #pragma unroll 4
    for (int t = 0; t < CL; ++t) {
        const float gg = sc_g[base + (size_t)t * Dd];
        const float uu = sc_u[base + (size_t)t * Dd];
        h = fmaf(gg, h, (1.0f - gg) * uu);
        sc_h[base + (size_t)t * Dd] = f2tf_f(h);
    }
}

// ---------------------------------------------------------------------------
extern "C" void kernel_launch(void* const* d_in, const int* in_sizes, int n_in,
                              void* d_out, int out_size)
{
    (void)in_sizes; (void)n_in; (void)out_size;

    const float* x  = (const float*)d_in[0];
    const float* Wi = (const float*)d_in[1];
    const float* bi = (const float*)d_in[2];
    const float* Wg = (const float*)d_in[3];
    const float* bg = (const float*)d_in[4];
    const float* Wo = (const float*)d_in[5];
    const float* bo = (const float*)d_in[6];
    float* out = (float*)d_out;

    float *u, *g, *h, *xt, *wt;
    cudaGetSymbolAddress((void**)&u,  sc_u);
    cudaGetSymbolAddress((void**)&g,  sc_g);
    cudaGetSymbolAddress((void**)&h,  sc_h);
    cudaGetSymbolAddress((void**)&xt, sc_xt);
    cudaGetSymbolAddress((void**)&wt, sc_wt);
    float* wti = wt;
    float* wtg = wt + (size_t)Dd * Dd;
    float* wto = wt + 2 * (size_t)Dd * Dd;

    cudaFuncSetAttribute(gemm_tc, cudaFuncAttributeMaxDynamicSharedMemorySize, SMEM_BYTES);

    // pre-round operands to tf32 bits
    round_tf32_k<<<4096, 256>>>((const float4*)x,  (float4*)xt,  Mtot * Dd / 4);
    round_tf32_k<<<512, 256>>>((const float4*)Wi, (float4*)wti, Dd * Dd / 4);
    round_tf32_k<<<512, 256>>>((const float4*)Wg, (float4*)wtg, Dd * Dd / 4);
    round_tf32_k<<<512, 256>>>((const float4*)Wo, (float4*)wto, Dd * Dd / 4);

    const dim3 ggrid(Dd / BN, Mtot / BM);   // (8, 256)
    const dim3 gblk(256);

    gemm_tc<<<ggrid, gblk, SMEM_BYTES>>>(xt, wti, bi, u, 0);
    gemm_tc<<<ggrid, gblk, SMEM_BYTES>>>(xt, wtg, bg, g, 1);

    const dim3 s_grid(Dd / 256, NC, Bb);    // (4, 32, 8)
    scan_phase1<<<s_grid, 256>>>();
    scan_phase2<<<32, 256>>>();
    scan_phase3<<<s_grid, 256>>>();

    gemm_tc<<<ggrid, gblk, SMEM_BYTES>>>(h, wto, bo, out, 0);
}